// round 15
// baseline (speedup 1.0000x reference)
#include <cuda_runtime.h>
#include <mma.h>
#include <cstdint>

using namespace nvcuda;

#define NNODES 50000
#define MPAD   50048
#define FDIM   128
#define KNB    32
#define EDIM   16
#define KK     2048          // FDIM * EDIM
#define GRID1  888           // stage-1 persistent CTAs (6/SM)

__device__ float g_buf[(size_t)MPAD * KK];   // [i][l*16+n], pad rows stay 0
__device__ float W2[KK * FDIM];              // [k=(l*16+n)][m]
__device__ int   g_nlist_is64;

// ---------------------------------------------------------------------------
__global__ void detect_nlist(const int* __restrict__ nl) {
    int odd_or = 0;
#pragma unroll
    for (int t = 1; t < 64; t += 2) odd_or |= nl[t];
    g_nlist_is64 = (odd_or == 0) ? 1 : 0;
}

// W2[(l*16+n)*128 + m] = tf32(w[l,m,n])
__global__ void build_w2(const float* __restrict__ w) {
    int idx = blockIdx.x * 256 + threadIdx.x;
    if (idx < KK * FDIM) {
        int m = idx & (FDIM - 1);
        int k = idx >> 7;
        int l = k >> 4;
        int n = k & (EDIM - 1);
        W2[idx] = wmma::__float_to_tf32(w[(size_t)l * FDIM * EDIM + (size_t)m * EDIM + n]);
    }
}

// ---------------------------------------------------------------------------
__device__ __forceinline__ void cp16(void* s, const void* g) {
    uint32_t sa = (uint32_t)__cvta_generic_to_shared(s);
    asm volatile("cp.async.cg.shared.global [%0], [%1], 16;\n" :: "r"(sa), "l"(g));
}
__device__ __forceinline__ void cp_commit() { asm volatile("cp.async.commit_group;\n"); }
template <int N>
__device__ __forceinline__ void cp_wait() { asm volatile("cp.async.wait_group %0;\n" :: "n"(N)); }

// ---------------------------------------------------------------------------
// Stage 1: cp.async-pipelined gather + scalar FFMA2 contraction (fp32-exact).
//   g[i, l*16+n] = tf32_rn( sum_j nodes[nlist[i,j], l] * edges[i,j,n] )
// Persistent CTAs (grid-stride), double-buffered one node ahead; compute
// reads gathered rows from smem (no LDG latency in the FMA loop).
// ---------------------------------------------------------------------------
__global__ __launch_bounds__(128) void gather_contract(const float* __restrict__ nodes,
                                                       const int*   __restrict__ nl32,
                                                       const float* __restrict__ edges) {
    __shared__ __align__(16) float nb[2][KNB][FDIM];  // gathered rows, 2x16KB
    __shared__ __align__(16) float eg[2][512];        // edges[i], 2x2KB
    __shared__ int snb[2][KNB];

    const int tid  = threadIdx.x;   // = l
    const int strd = gridDim.x;
    const bool is64 = (g_nlist_is64 != 0);

    auto ldidx = [&](long long pos) -> int {
        int idx = is64 ? nl32[2 * pos] : nl32[pos];
        return idx < 0 ? 0 : (idx >= NNODES ? NNODES - 1 : idx);
    };
    auto issue_node = [&](int node, int buf) {
        cp16(&eg[buf][tid * 4], edges + (size_t)node * 512 + tid * 4);
#pragma unroll
        for (int u = 0; u < 8; u++) {
            int q = tid + u * 128;
            int row = q >> 5, seg = q & 31;
            cp16(&nb[buf][row][seg * 4],
                 nodes + (size_t)snb[buf][row] * FDIM + seg * 4);
        }
    };

    int i0 = blockIdx.x;
    if (i0 >= NNODES) return;
    if (tid < KNB) snb[0][tid] = ldidx((long long)i0 * KNB + tid);
    __syncthreads();
    issue_node(i0, 0);
    cp_commit();
    if (i0 + strd < NNODES && tid < KNB)
        snb[1][tid] = ldidx((long long)(i0 + strd) * KNB + tid);

    const uint32_t eg_base = (uint32_t)__cvta_generic_to_shared(&eg[0][0]);

    for (int it = 0;; it++) {
        int i = i0 + it * strd;
        if (i >= NNODES) break;
        int b = it & 1;
        int inext = i + strd;

        __syncthreads();   // snb[b^1] visible; buffer b^1 consumed by it-1
        if (inext < NNODES) issue_node(inext, b ^ 1);
        cp_commit();
        int i2 = i + 2 * strd;
        if (i2 < NNODES && tid < KNB)
            snb[b][tid] = ldidx((long long)i2 * KNB + tid);

        cp_wait<1>();      // node i's data landed (inext's may still be in flight)
        __syncthreads();

        // Compute: 8 packed f32x2 accumulator chains over 32 neighbors.
        unsigned long long acc2[8];
#pragma unroll
        for (int q = 0; q < 8; q++) acc2[q] = 0ULL;

        const uint32_t eb = eg_base + (uint32_t)(b * 2048);
#pragma unroll 8
        for (int j = 0; j < KNB; j++) {
            float v = nb[b][j][tid];          // conflict-free LDS.32
            unsigned long long vv;
            asm("mov.b64 %0, {%1, %1};" : "=l"(vv) : "f"(v));
            uint32_t ja = eb + j * (EDIM * 4);
#pragma unroll
            for (int q = 0; q < 4; q++) {
                unsigned long long e0, e1;
                asm("ld.shared.v2.u64 {%0, %1}, [%2];"
                    : "=l"(e0), "=l"(e1) : "r"(ja + q * 16));
                asm("fma.rn.f32x2 %0, %1, %2, %3;"
                    : "=l"(acc2[2 * q])     : "l"(vv), "l"(e0), "l"(acc2[2 * q]));
                asm("fma.rn.f32x2 %0, %1, %2, %3;"
                    : "=l"(acc2[2 * q + 1]) : "l"(vv), "l"(e1), "l"(acc2[2 * q + 1]));
            }
        }

        float accf[16];
#pragma unroll
        for (int q = 0; q < 8; q++) {
            float lo, hi;
            asm("mov.b64 {%0, %1}, %2;" : "=f"(lo), "=f"(hi) : "l"(acc2[q]));
            accf[2 * q]     = wmma::__float_to_tf32(lo);
            accf[2 * q + 1] = wmma::__float_to_tf32(hi);
        }
        float4* g4 = (float4*)(g_buf + (size_t)i * KK + (size_t)tid * EDIM);
#pragma unroll
        for (int q = 0; q < 4; q++)
            g4[q] = make_float4(accf[q * 4 + 0], accf[q * 4 + 1],
                                accf[q * 4 + 2], accf[q * 4 + 3]);
    }
}

// ---------------------------------------------------------------------------
// Stage 2: C = (1/32) * g_buf @ W2  (M=50048, N=128, K=2048), tf32 wmma.
// BM=128, BN=128, BK=32, 3-stage cp.async ring, 1 sync/iter, 64 iters.
// (unchanged from R14 — measured 388us)
// ---------------------------------------------------------------------------
#define BK2        32
#define STAGES     3
#define AS_STRIDE  36
#define AS_BYTES   (128 * AS_STRIDE * 4)       // 18432
#define BS_STRIDE  132
#define BS_BYTES   (BK2 * BS_STRIDE * 4)       // 16896
#define STAGE_BYTES (AS_BYTES + BS_BYTES)      // 35328
#define S2_SMEM    (STAGES * STAGE_BYTES)      // 105984

__global__ __launch_bounds__(256, 2) void gemm_tf32(float* __restrict__ out) {
    extern __shared__ __align__(16) char s2mem[];

    const int tid = threadIdx.x;
    const int wid = tid >> 5;
    const int warp_m = wid >> 1;   // 0..3
    const int warp_n = wid & 1;    // 0..1
    const size_t row0 = (size_t)blockIdx.x * 128;

    auto Asm = [&](int s) -> float* { return (float*)(s2mem + s * STAGE_BYTES); };
    auto Bsm = [&](int s) -> float* { return (float*)(s2mem + s * STAGE_BYTES + AS_BYTES); };

    wmma::fragment<wmma::accumulator, 16, 16, 8, float> c[2][4];
#pragma unroll
    for (int mi = 0; mi < 2; mi++)
#pragma unroll
        for (int ni = 0; ni < 4; ni++) wmma::fill_fragment(c[mi][ni], 0.0f);

    auto load_tiles = [&](int s, int kb) {
        const float* Ab = g_buf + row0 * KK + (size_t)(kb * BK2);
        const float* Bb = W2 + (size_t)(kb * BK2) * FDIM;
        float* A = Asm(s);
        float* B = Bsm(s);
#pragma unroll
        for (int u = 0; u < 4; u++) {          // A: 128 x 32 -> 1024 float4
            int q = tid + u * 256;
            int ar = q >> 3, ac = q & 7;
            cp16(A + ar * AS_STRIDE + ac * 4, Ab + (size_t)ar * KK + ac * 4);
        }
#pragma unroll
        for (int u = 0; u < 4; u++) {          // B: 32 x 128 -> 1024 float4
            int q = tid + u * 256;
            int br = q >> 5, bc = q & 31;
            cp16(B + br * BS_STRIDE + bc * 4, Bb + br * FDIM + bc * 4);
        }
        cp_commit();
    };

    load_tiles(0, 0);
    load_tiles(1, 1);

    const int nkb = KK / BK2;  // 64
    for (int kb = 0; kb < nkb; kb++) {
        int cur = kb % STAGES;

        if (kb + 1 < nkb) cp_wait<1>();
        else              cp_wait<0>();
        __syncthreads();

        if (kb + 2 < nkb) load_tiles((kb + 2) % STAGES, kb + 2);

        const float* A = Asm(cur);
        const float* B = Bsm(cur);
#pragma unroll
        for (int kk = 0; kk < 4; kk++) {
            wmma::fragment<wmma::matrix_a, 16, 16, 8, wmma::precision::tf32, wmma::row_major> a[2];
            wmma::fragment<wmma::matrix_b, 16, 16, 8, wmma::precision::tf32, wmma::row_major> b[4];
#pragma unroll
            for (int mi = 0; mi < 2; mi++)
                wmma::load_matrix_sync(a[mi],
                    A + (warp_m * 32 + mi * 16) * AS_STRIDE + kk * 8, AS_STRIDE);
#pragma unroll
            for (int ni = 0; ni < 4; ni++)
                wmma::load_matrix_sync(b[ni],
                    B + (kk * 8) * BS_STRIDE + warp_n * 64 + ni * 16, BS_STRIDE);
#pragma unroll
            for (int mi = 0; mi < 2; mi++)
#pragma unroll
                for (int ni = 0; ni < 4; ni++)
                    wmma::mma_sync(c[mi][ni], a[mi], b[ni], c[mi][ni]);
        }
    }

    const float scale = 1.0f / (float)KNB;
#pragma unroll
    for (int mi = 0; mi < 2; mi++)
#pragma unroll
        for (int ni = 0; ni < 4; ni++) {
#pragma unroll
            for (int t = 0; t < c[mi][ni].num_elements; t++) c[mi][ni].x[t] *= scale;
            size_t rglob = row0 + warp_m * 32 + mi * 16;
            if (rglob < NNODES)   // 16-row fragments fully valid (80 % 16 == 0)
                wmma::store_matrix_sync(out + rglob * FDIM + warp_n * 64 + ni * 16,
                                        c[mi][ni], FDIM, wmma::mem_row_major);
        }
}

// ---------------------------------------------------------------------------
extern "C" void kernel_launch(void* const* d_in, const int* in_sizes, int n_in,
                              void* d_out, int out_size) {
    const float* nodes = nullptr;
    const int*   nlist = nullptr;
    const float* edges = nullptr;
    const float* w     = nullptr;
    for (int t = 0; t < n_in; t++) {
        long long s = in_sizes[t];
        if      (s == (long long)NNODES * FDIM)        nodes = (const float*)d_in[t];
        else if (s == (long long)NNODES * KNB)         nlist = (const int*)d_in[t];
        else if (s == (long long)NNODES * KNB * EDIM)  edges = (const float*)d_in[t];
        else if (s == (long long)FDIM * FDIM * EDIM)   w     = (const float*)d_in[t];
    }
    if (!nodes) nodes = (const float*)d_in[0];
    if (!nlist) nlist = (const int*)d_in[1];
    if (!edges) edges = (const float*)d_in[2];
    if (!w)     w     = (const float*)d_in[3];

    float* out = (float*)d_out;

    static bool attr_done = false;
    if (!attr_done) {
        cudaFuncSetAttribute(gemm_tf32,
                             cudaFuncAttributeMaxDynamicSharedMemorySize, S2_SMEM);
        attr_done = true;
    }

    detect_nlist<<<1, 1>>>(nlist);
    build_w2<<<(KK * FDIM + 255) / 256, 256>>>(w);
    gather_contract<<<GRID1, 128>>>(nodes, nlist, edges);
    gemm_tf32<<<MPAD / 128, 256, S2_SMEM>>>(out);
}